// round 1
// baseline (speedup 1.0000x reference)
#include <cuda_runtime.h>
#include <cstdint>

#define N     8192
#define E     262144
#define D     128
#define HMLP  256
#define KEEP  131072
#define CHUNK 1024
#define EQCAP 4096

// ------------------- device scratch (static, no allocs) -------------------
__device__ float    d_XW[N * D];          // X @ W_gnn            (4 MB)
__device__ float    d_Hv[N * D];          // relu(A@XW + b)       (4 MB)
__device__ float    d_G [N * HMLP];       // H_v @ W1[0:128]      (8 MB)
__device__ float    d_part[64 * D];
__device__ float    d_hG[D];
__device__ float    d_cb[HMLP];
__device__ unsigned d_key[E];             // sortable fp32 keys
__device__ int      d_row_cnt[N];
__device__ int      d_row_cur[N];
__device__ int      d_row_start[N + 1];
__device__ int      d_perm[E];
__device__ unsigned d_hist[256];
__device__ unsigned d_prefix;
__device__ unsigned d_krem;
__device__ int      d_eq_cnt;
__device__ int      d_eq_list[EQCAP];

// ------------------- small init kernels -------------------
__global__ void zero_out_kernel(float4* out) {
    const int total = (N * (long long)N) / 4;   // 16M float4
    for (int idx = blockIdx.x * blockDim.x + threadIdx.x; idx < total;
         idx += gridDim.x * blockDim.x)
        out[idx] = make_float4(0.f, 0.f, 0.f, 0.f);
}

__global__ void zero_ints_kernel() {
    for (int t = blockIdx.x * blockDim.x + threadIdx.x; t < 2 * N;
         t += gridDim.x * blockDim.x) {
        if (t < N) d_row_cnt[t] = 0;
        else       d_row_cur[t - N] = 0;
    }
}

__global__ void init_sel_kernel() {
    d_prefix = 0u;
    d_krem   = KEEP;
    d_eq_cnt = 0;
}

__global__ void zero_hist_kernel() { d_hist[threadIdx.x] = 0u; }

// ------------------- 1) XW = X @ W_gnn -------------------
__global__ void xw_kernel(const float* __restrict__ X, const float* __restrict__ W) {
    __shared__ float xs[D];
    int i = blockIdx.x, d = threadIdx.x;          // 128 threads
    xs[d] = X[i * D + d];
    __syncthreads();
    float acc = 0.f;
#pragma unroll 8
    for (int k = 0; k < D; k++) acc = fmaf(xs[k], W[k * D + d], acc);
    d_XW[i * D + d] = acc;
}

// ------------------- 2) CSR build -------------------
__global__ void hist_ei_kernel(const int* __restrict__ ei) {
    int e = blockIdx.x * blockDim.x + threadIdx.x;
    if (e < E) atomicAdd(&d_row_cnt[ei[e]], 1);
}

__global__ void csr_scan_kernel() {                 // 1 block, 1024 threads
    __shared__ int sh[1024];
    int t = threadIdx.x;
    int loc[8]; int s = 0;
#pragma unroll
    for (int k = 0; k < 8; k++) { loc[k] = s; s += d_row_cnt[t * 8 + k]; }
    sh[t] = s;
    __syncthreads();
    int own = s;
    for (int off = 1; off < 1024; off <<= 1) {
        int v = (t >= off) ? sh[t - off] : 0;
        __syncthreads();
        sh[t] += v;
        __syncthreads();
    }
    int excl = sh[t] - own;
#pragma unroll
    for (int k = 0; k < 8; k++) d_row_start[t * 8 + k] = excl + loc[k];
    if (t == 1023) d_row_start[N] = sh[1023];
}

__global__ void scatter_perm_kernel(const int* __restrict__ ei) {
    int e = blockIdx.x * blockDim.x + threadIdx.x;
    if (e < E) {
        int i   = ei[e];
        int pos = d_row_start[i] + atomicAdd(&d_row_cur[i], 1);
        d_perm[pos] = e;
    }
}

// ------------------- 3) H_v rows: sparse A@XW + relu (dedup'd) -------------------
__global__ void __launch_bounds__(128) gnn_row_kernel(const float* __restrict__ A,
                                                      const int*   __restrict__ ej,
                                                      const float* __restrict__ b_gnn) {
    __shared__ unsigned bm[256];     // 8192-bit dedupe bitmap over j
    __shared__ int      sj[CHUNK];
    __shared__ float    sw[CHUNK];
    int i = blockIdx.x, t = threadIdx.x;           // 128 threads, t = feature dim
    for (int k = t; k < 256; k += 128) bm[k] = 0u;
    int s0 = d_row_start[i], s1 = d_row_start[i + 1];
    __syncthreads();
    float acc = 0.f;
    for (int base = s0; base < s1; base += CHUNK) {
        int cnt = min(CHUNK, s1 - base);
        for (int s = t; s < cnt; s += 128) {
            int e = d_perm[base + s];
            int j = ej[e];
            unsigned old = atomicOr(&bm[j >> 5], 1u << (j & 31));
            bool dup = (old >> (j & 31)) & 1u;
            sj[s] = dup ? -1 : j;
            sw[s] = dup ? 0.f : A[(size_t)i * N + j];
        }
        __syncthreads();
        for (int s = 0; s < cnt; s++) {
            int j = sj[s];
            if (j >= 0) acc = fmaf(sw[s], d_XW[j * D + t], acc);
        }
        __syncthreads();
    }
    d_Hv[i * D + t] = fmaxf(acc + b_gnn[t], 0.f);
}

// ------------------- 4) h_G = mean over rows (deterministic 2-stage) -------------------
__global__ void hg1_kernel() {
    int b = blockIdx.x, d = threadIdx.x;           // 64 blocks x 128
    float acc = 0.f;
    for (int r = 0; r < 128; r++) acc += d_Hv[(b * 128 + r) * D + d];
    d_part[b * D + d] = acc;
}
__global__ void hg2_kernel() {
    int d = threadIdx.x;
    float acc = 0.f;
    for (int b = 0; b < 64; b++) acc += d_part[b * D + d];
    d_hG[d] = acc * (1.f / N);
}

// ------------------- 5) G = H_v @ W1[0:128,:] -------------------
__global__ void __launch_bounds__(256) g_kernel(const float* __restrict__ W1) {
    __shared__ float hs[D];
    int i = blockIdx.x, o = threadIdx.x;           // 256 threads
    if (o < D) hs[o] = d_Hv[i * D + o];
    __syncthreads();
    float acc = 0.f;
#pragma unroll 4
    for (int dd = 0; dd < D; dd++) acc = fmaf(hs[dd], W1[dd * HMLP + o], acc);
    d_G[(size_t)i * HMLP + o] = acc;
}

// ------------------- 6) cb = h_G @ W1[128:256,:] + W1[256,:] + b1 -------------------
__global__ void cb_kernel(const float* __restrict__ W1, const float* __restrict__ b1) {
    int o = threadIdx.x;                           // 256 threads, 1 block
    float acc = 0.f;
    for (int dd = 0; dd < D; dd++) acc = fmaf(d_hG[dd], W1[(D + dd) * HMLP + o], acc);
    d_cb[o] = acc + W1[(2 * D) * HMLP + o] + b1[o];
}

// ------------------- 7) per-edge scores (warp/edge) -------------------
__global__ void __launch_bounds__(256) score_kernel(const int*   __restrict__ ei,
                                                    const int*   __restrict__ ej,
                                                    const float* __restrict__ noise,
                                                    const float* __restrict__ W2,
                                                    const float* __restrict__ b2) {
    int gw   = (blockIdx.x * blockDim.x + threadIdx.x) >> 5;
    int lane = threadIdx.x & 31;
    if (gw >= E) return;
    int i = ei[gw], j = ej[gw];
    const float* gi = d_G + (size_t)i * HMLP;
    const float* gj = d_G + (size_t)j * HMLP;
    float acc = 0.f;
#pragma unroll
    for (int t = 0; t < 8; t++) {
        int o = lane + 32 * t;
        float h = fmaxf(gi[o] + gj[o] + d_cb[o], 0.f);
        acc = fmaf(h, W2[o], acc);
    }
    for (int off = 16; off; off >>= 1) acc += __shfl_xor_sync(0xFFFFFFFFu, acc, off);
    if (lane == 0) {
        float u = noise[gw];
        float g = -logf(-logf(u + 1e-8f) + 1e-8f);
        float s = acc + b2[0] + g;
        unsigned k = __float_as_uint(s);
        k = (k & 0x80000000u) ? ~k : (k | 0x80000000u);
        d_key[gw] = k;
    }
}

// ------------------- 8) radix select (k-th largest, MSB-first) -------------------
__global__ void hist_pass_kernel(int level) {
    __shared__ unsigned sh[256];
    int shift = 24 - 8 * level;
    unsigned himask = level ? (0xFFFFFFFFu << (shift + 8)) : 0u;
    unsigned pfx = d_prefix;
    for (int k = threadIdx.x; k < 256; k += blockDim.x) sh[k] = 0u;
    __syncthreads();
    for (int e = blockIdx.x * blockDim.x + threadIdx.x; e < E;
         e += gridDim.x * blockDim.x) {
        unsigned u = d_key[e];
        if ((u & himask) == pfx) atomicAdd(&sh[(u >> shift) & 255], 1u);
    }
    __syncthreads();
    for (int k = threadIdx.x; k < 256; k += blockDim.x)
        if (sh[k]) atomicAdd(&d_hist[k], sh[k]);
}

__global__ void scan_pass_kernel(int level) {       // 1 thread
    int shift = 24 - 8 * level;
    unsigned c = 0, krem = d_krem;
    for (int b = 255; b >= 0; b--) {
        unsigned h = d_hist[b];
        if (c + h >= krem) {
            d_prefix |= ((unsigned)b) << shift;
            d_krem = krem - c;
            return;
        }
        c += h;
    }
}

// ------------------- 9) output scatter -------------------
__global__ void eq_collect_kernel() {
    unsigned th = d_prefix;
    for (int e = blockIdx.x * blockDim.x + threadIdx.x; e < E;
         e += gridDim.x * blockDim.x) {
        if (d_key[e] == th) {
            int p = atomicAdd(&d_eq_cnt, 1);
            if (p < EQCAP) d_eq_list[p] = e;
        }
    }
}

__global__ void scatter_gt_kernel(const float* __restrict__ A,
                                  const int* __restrict__ ei, const int* __restrict__ ej,
                                  float* __restrict__ out) {
    unsigned th = d_prefix;
    for (int e = blockIdx.x * blockDim.x + threadIdx.x; e < E;
         e += gridDim.x * blockDim.x) {
        if (d_key[e] > th) {
            int i = ei[e], j = ej[e];
            out[(size_t)i * N + j] = A[(size_t)i * N + j];
        }
    }
}

__global__ void scatter_eq_kernel(const float* __restrict__ A,
                                  const int* __restrict__ ei, const int* __restrict__ ej,
                                  float* __restrict__ out) {
    int cnt  = min(d_eq_cnt, EQCAP);
    int need = (int)d_krem;                        // ties broken by lowest edge index
    int tid  = blockIdx.x * blockDim.x + threadIdx.x;
    if (tid >= cnt) return;
    int my = d_eq_list[tid];
    int r = 0;
    for (int t = 0; t < cnt; t++) r += (d_eq_list[t] < my);
    if (r < need) {
        int i = ei[my], j = ej[my];
        out[(size_t)i * N + j] = A[(size_t)i * N + j];
    }
}

// ------------------- launch -------------------
extern "C" void kernel_launch(void* const* d_in, const int* in_sizes, int n_in,
                              void* d_out, int out_size) {
    const float* A      = (const float*)d_in[0];
    const float* X      = (const float*)d_in[1];
    const int*   ei     = (const int*)  d_in[2];
    const int*   ej     = (const int*)  d_in[3];
    const float* noise  = (const float*)d_in[4];
    const float* W_gnn  = (const float*)d_in[5];
    const float* b_gnn  = (const float*)d_in[6];
    const float* W1     = (const float*)d_in[7];
    const float* b1     = (const float*)d_in[8];
    const float* W2     = (const float*)d_in[9];
    const float* b2     = (const float*)d_in[10];
    float* out = (float*)d_out;

    zero_out_kernel<<<4096, 256>>>((float4*)out);
    zero_ints_kernel<<<64, 256>>>();
    init_sel_kernel<<<1, 1>>>();

    xw_kernel<<<N, D>>>(X, W_gnn);

    hist_ei_kernel<<<E / 256, 256>>>(ei);
    csr_scan_kernel<<<1, 1024>>>();
    scatter_perm_kernel<<<E / 256, 256>>>(ei);

    gnn_row_kernel<<<N, 128>>>(A, ej, b_gnn);

    hg1_kernel<<<64, 128>>>();
    hg2_kernel<<<1, 128>>>();

    g_kernel<<<N, 256>>>(W1);
    cb_kernel<<<1, 256>>>(W1, b1);

    score_kernel<<<E * 32 / 256, 256>>>(ei, ej, noise, W2, b2);

    for (int level = 0; level < 4; level++) {
        zero_hist_kernel<<<1, 256>>>();
        hist_pass_kernel<<<512, 256>>>(level);
        scan_pass_kernel<<<1, 1>>>(level);
    }

    eq_collect_kernel<<<512, 256>>>();
    scatter_gt_kernel<<<1024, 256>>>(A, ei, ej, out);
    scatter_eq_kernel<<<4, 1024>>>(A, ei, ej, out);
}

// round 2
// speedup vs baseline: 1.2298x; 1.2298x over previous
#include <cuda_runtime.h>
#include <cstdint>

#define N     8192
#define E     262144
#define D     128
#define HMLP  256
#define KEEP  131072
#define CHUNK 1024
#define EQCAP 4096

// ------------------- device scratch (static, no allocs) -------------------
__device__ float    d_XW[N * D];          // X @ W_gnn            (4 MB)
__device__ float    d_Hv[N * D];          // relu(A@XW + b)       (4 MB)
__device__ float    d_G [N * HMLP];       // H_v @ W1[0:128]      (8 MB)
__device__ float    d_part[64 * D];
__device__ float    d_cb[HMLP];
__device__ unsigned d_key[E];             // sortable fp32 keys
__device__ int      d_row_cnt[N];
__device__ int      d_row_cur[N];
__device__ int      d_row_start[N + 1];
__device__ int      d_perm[E];
__device__ unsigned d_hist4[4][256];
__device__ unsigned d_prefix;
__device__ unsigned d_krem;
__device__ int      d_eq_cnt;
__device__ int      d_eq_list[EQCAP];

// ------------------- init (counts, selection state, all 4 histograms) -------------------
__global__ void init_kernel() {
    int t = blockIdx.x * blockDim.x + threadIdx.x;
    for (int k = t; k < 2 * N; k += gridDim.x * blockDim.x) {
        if (k < N) d_row_cnt[k] = 0;
        else       d_row_cur[k - N] = 0;
    }
    if (t < 1024) ((unsigned*)d_hist4)[t] = 0u;
    if (t == 0) { d_prefix = 0u; d_krem = KEEP; d_eq_cnt = 0; }
}

// ------------------- tiled SGEMM: C[M,NTOT] = A[M,128] @ B[128,NTOT] -------------------
// tile: 64 rows x 128 cols, 256 threads, micro 4x8, K-step 16
__global__ void __launch_bounds__(256) sgemm_kernel(const float* __restrict__ A,
                                                    const float* __restrict__ B,
                                                    float* __restrict__ C, int NTOT) {
    __shared__ float As[16][65];
    __shared__ float Bs[16][128];
    int t   = threadIdx.x;
    int tx  = t & 15;          // 16 col-groups (8 cols each)
    int ty  = t >> 4;          // 16 row-groups (4 rows each)
    int r0  = blockIdx.x * 64;
    int n0  = blockIdx.y * 128;

    float acc[4][8];
#pragma unroll
    for (int r = 0; r < 4; r++)
#pragma unroll
        for (int c = 0; c < 8; c++) acc[r][c] = 0.f;

    for (int k0 = 0; k0 < D; k0 += 16) {
        // load A tile: 64 rows x 16 k, thread t -> row t>>2, k quad t&3
        {
            int m  = t >> 2;
            int kq = (t & 3) * 4;
            float4 v = *(const float4*)&A[(size_t)(r0 + m) * D + k0 + kq];
            As[kq + 0][m] = v.x; As[kq + 1][m] = v.y;
            As[kq + 2][m] = v.z; As[kq + 3][m] = v.w;
        }
        // load B tile: 16 k x 128 cols
        {
            int kb = t >> 4;
            int nb = (t & 15) * 8;
            float4 v0 = *(const float4*)&B[(size_t)(k0 + kb) * NTOT + n0 + nb];
            float4 v1 = *(const float4*)&B[(size_t)(k0 + kb) * NTOT + n0 + nb + 4];
            *(float4*)&Bs[kb][nb]     = v0;
            *(float4*)&Bs[kb][nb + 4] = v1;
        }
        __syncthreads();
#pragma unroll
        for (int k = 0; k < 16; k++) {
            float a0 = As[k][ty * 4 + 0], a1 = As[k][ty * 4 + 1];
            float a2 = As[k][ty * 4 + 2], a3 = As[k][ty * 4 + 3];
            float4 b0 = *(float4*)&Bs[k][tx * 8];
            float4 b1 = *(float4*)&Bs[k][tx * 8 + 4];
            float bb[8] = {b0.x, b0.y, b0.z, b0.w, b1.x, b1.y, b1.z, b1.w};
#pragma unroll
            for (int c = 0; c < 8; c++) {
                acc[0][c] = fmaf(a0, bb[c], acc[0][c]);
                acc[1][c] = fmaf(a1, bb[c], acc[1][c]);
                acc[2][c] = fmaf(a2, bb[c], acc[2][c]);
                acc[3][c] = fmaf(a3, bb[c], acc[3][c]);
            }
        }
        __syncthreads();
    }
#pragma unroll
    for (int r = 0; r < 4; r++) {
        float* cp = &C[(size_t)(r0 + ty * 4 + r) * NTOT + n0 + tx * 8];
        *(float4*)cp       = make_float4(acc[r][0], acc[r][1], acc[r][2], acc[r][3]);
        *(float4*)(cp + 4) = make_float4(acc[r][4], acc[r][5], acc[r][6], acc[r][7]);
    }
}

// ------------------- CSR build -------------------
__global__ void hist_ei_kernel(const int* __restrict__ ei) {
    int e = blockIdx.x * blockDim.x + threadIdx.x;
    if (e < E) atomicAdd(&d_row_cnt[ei[e]], 1);
}

__global__ void csr_scan_kernel() {                 // 1 block, 1024 threads
    __shared__ int sh[1024];
    int t = threadIdx.x;
    int loc[8]; int s = 0;
#pragma unroll
    for (int k = 0; k < 8; k++) { loc[k] = s; s += d_row_cnt[t * 8 + k]; }
    sh[t] = s;
    __syncthreads();
    int own = s;
    for (int off = 1; off < 1024; off <<= 1) {
        int v = (t >= off) ? sh[t - off] : 0;
        __syncthreads();
        sh[t] += v;
        __syncthreads();
    }
    int excl = sh[t] - own;
#pragma unroll
    for (int k = 0; k < 8; k++) d_row_start[t * 8 + k] = excl + loc[k];
    if (t == 1023) d_row_start[N] = sh[1023];
}

__global__ void scatter_perm_kernel(const int* __restrict__ ei) {
    int e = blockIdx.x * blockDim.x + threadIdx.x;
    if (e < E) {
        int i   = ei[e];
        int pos = d_row_start[i] + atomicAdd(&d_row_cur[i], 1);
        d_perm[pos] = e;
    }
}

// ------------------- H_v rows: sparse A@XW + relu (dedup'd) -------------------
__global__ void __launch_bounds__(128) gnn_row_kernel(const float* __restrict__ A,
                                                      const int*   __restrict__ ej,
                                                      const float* __restrict__ b_gnn) {
    __shared__ unsigned bm[256];     // 8192-bit dedupe bitmap over j
    __shared__ int      sj[CHUNK];
    __shared__ float    sw[CHUNK];
    int i = blockIdx.x, t = threadIdx.x;           // 128 threads, t = feature dim
    for (int k = t; k < 256; k += 128) bm[k] = 0u;
    int s0 = d_row_start[i], s1 = d_row_start[i + 1];
    __syncthreads();
    float acc = 0.f;
    for (int base = s0; base < s1; base += CHUNK) {
        int cnt = min(CHUNK, s1 - base);
        for (int s = t; s < cnt; s += 128) {
            int e = d_perm[base + s];
            int j = ej[e];
            unsigned old = atomicOr(&bm[j >> 5], 1u << (j & 31));
            bool dup = (old >> (j & 31)) & 1u;
            sj[s] = dup ? -1 : j;
            sw[s] = dup ? 0.f : A[(size_t)i * N + j];
        }
        __syncthreads();
        for (int s = 0; s < cnt; s++) {
            int j = sj[s];
            if (j >= 0) acc = fmaf(sw[s], d_XW[j * D + t], acc);
        }
        __syncthreads();
    }
    d_Hv[i * D + t] = fmaxf(acc + b_gnn[t], 0.f);
}

// ------------------- h_G partials + fused (mean + cb) -------------------
__global__ void hg1_kernel() {
    int b = blockIdx.x, d = threadIdx.x;           // 64 blocks x 128
    float acc = 0.f;
    for (int r = 0; r < 128; r++) acc += d_Hv[(b * 128 + r) * D + d];
    d_part[b * D + d] = acc;
}

__global__ void hg2cb_kernel(const float* __restrict__ W1, const float* __restrict__ b1) {
    __shared__ float hg[D];
    int t = threadIdx.x;                           // 256 threads, 1 block
    if (t < D) {
        float acc = 0.f;
        for (int b = 0; b < 64; b++) acc += d_part[b * D + t];
        hg[t] = acc * (1.f / N);
    }
    __syncthreads();
    float acc = 0.f;
    for (int dd = 0; dd < D; dd++) acc = fmaf(hg[dd], W1[(D + dd) * HMLP + t], acc);
    d_cb[t] = acc + W1[(2 * D) * HMLP + t] + b1[t];
}

// ------------------- per-edge scores, CSR-ordered (row i cached in smem) -------------------
__global__ void __launch_bounds__(256) score_csr_kernel(const int*   __restrict__ ej,
                                                        const float* __restrict__ noise,
                                                        const float* __restrict__ W2,
                                                        const float* __restrict__ b2) {
    __shared__ float gis[HMLP];
    __shared__ float cbs[HMLP];
    __shared__ float w2s[HMLP];
    int i  = blockIdx.x;
    int s0 = d_row_start[i], s1 = d_row_start[i + 1];
    if (s0 == s1) return;
    int t = threadIdx.x;
    gis[t] = d_G[(size_t)i * HMLP + t];
    cbs[t] = d_cb[t];
    w2s[t] = W2[t];
    __syncthreads();
    int warp = t >> 5, lane = t & 31;
    float b2v = b2[0];
    for (int idx = s0 + warp; idx < s1; idx += 8) {
        int e = d_perm[idx];
        int j = ej[e];
        const float* gj = d_G + (size_t)j * HMLP;
        float acc = 0.f;
#pragma unroll
        for (int q = 0; q < 8; q++) {
            int o = lane + 32 * q;
            float h = fmaxf((gis[o] + __ldg(&gj[o])) + cbs[o], 0.f);
            acc = fmaf(h, w2s[o], acc);
        }
        for (int off = 16; off; off >>= 1) acc += __shfl_xor_sync(0xFFFFFFFFu, acc, off);
        if (lane == 0) {
            float u = noise[e];
            float g = -logf(-logf(u + 1e-8f) + 1e-8f);
            float s = acc + b2v + g;
            unsigned k = __float_as_uint(s);
            k = (k & 0x80000000u) ? ~k : (k | 0x80000000u);
            d_key[e] = k;
        }
    }
}

// ------------------- radix select (k-th largest, MSB-first) -------------------
__global__ void hist_pass_kernel(int level) {
    __shared__ unsigned sh[256];
    int shift = 24 - 8 * level;
    unsigned himask = level ? (0xFFFFFFFFu << (shift + 8)) : 0u;
    unsigned pfx = d_prefix;
    for (int k = threadIdx.x; k < 256; k += blockDim.x) sh[k] = 0u;
    __syncthreads();
    for (int e = blockIdx.x * blockDim.x + threadIdx.x; e < E;
         e += gridDim.x * blockDim.x) {
        unsigned u = d_key[e];
        if ((u & himask) == pfx) atomicAdd(&sh[(u >> shift) & 255], 1u);
    }
    __syncthreads();
    for (int k = threadIdx.x; k < 256; k += blockDim.x)
        if (sh[k]) atomicAdd(&d_hist4[level][k], sh[k]);
}

__global__ void scan_pass_kernel(int level) {       // 1 thread
    int shift = 24 - 8 * level;
    unsigned c = 0, krem = d_krem;
    for (int b = 255; b >= 0; b--) {
        unsigned h = d_hist4[level][b];
        if (c + h >= krem) {
            d_prefix |= ((unsigned)b) << shift;
            d_krem = krem - c;
            return;
        }
        c += h;
    }
}

// ------------------- output scatter (gt + eq-collect fused) -------------------
__global__ void scatter_gt_eq_kernel(const float* __restrict__ A,
                                     const int* __restrict__ ei, const int* __restrict__ ej,
                                     float* __restrict__ out) {
    unsigned th = d_prefix;
    for (int e = blockIdx.x * blockDim.x + threadIdx.x; e < E;
         e += gridDim.x * blockDim.x) {
        unsigned u = d_key[e];
        if (u > th) {
            int i = ei[e], j = ej[e];
            out[(size_t)i * N + j] = A[(size_t)i * N + j];
        } else if (u == th) {
            int p = atomicAdd(&d_eq_cnt, 1);
            if (p < EQCAP) d_eq_list[p] = e;
        }
    }
}

__global__ void scatter_eq_kernel(const float* __restrict__ A,
                                  const int* __restrict__ ei, const int* __restrict__ ej,
                                  float* __restrict__ out) {
    int cnt  = min(d_eq_cnt, EQCAP);
    int need = (int)d_krem;                        // ties broken by lowest edge index
    int tid  = blockIdx.x * blockDim.x + threadIdx.x;
    if (tid >= cnt) return;
    int my = d_eq_list[tid];
    int r = 0;
    for (int t = 0; t < cnt; t++) r += (d_eq_list[t] < my);
    if (r < need) {
        int i = ei[my], j = ej[my];
        out[(size_t)i * N + j] = A[(size_t)i * N + j];
    }
}

// ------------------- launch -------------------
extern "C" void kernel_launch(void* const* d_in, const int* in_sizes, int n_in,
                              void* d_out, int out_size) {
    const float* A      = (const float*)d_in[0];
    const float* X      = (const float*)d_in[1];
    const int*   ei     = (const int*)  d_in[2];
    const int*   ej     = (const int*)  d_in[3];
    const float* noise  = (const float*)d_in[4];
    const float* W_gnn  = (const float*)d_in[5];
    const float* b_gnn  = (const float*)d_in[6];
    const float* W1     = (const float*)d_in[7];
    const float* b1     = (const float*)d_in[8];
    const float* W2     = (const float*)d_in[9];
    const float* b2     = (const float*)d_in[10];
    float* out = (float*)d_out;

    cudaMemsetAsync(out, 0, (size_t)N * N * sizeof(float));
    init_kernel<<<64, 256>>>();

    float* xw_p; cudaGetSymbolAddress((void**)&xw_p, d_XW);
    float* hv_p; cudaGetSymbolAddress((void**)&hv_p, d_Hv);
    float* g_p;  cudaGetSymbolAddress((void**)&g_p,  d_G);

    sgemm_kernel<<<dim3(N / 64, 1), 256>>>(X, W_gnn, xw_p, D);

    hist_ei_kernel<<<E / 256, 256>>>(ei);
    csr_scan_kernel<<<1, 1024>>>();
    scatter_perm_kernel<<<E / 256, 256>>>(ei);

    gnn_row_kernel<<<N, 128>>>(A, ej, b_gnn);

    hg1_kernel<<<64, 128>>>();
    hg2cb_kernel<<<1, 256>>>(W1, b1);

    sgemm_kernel<<<dim3(N / 64, 2), 256>>>(hv_p, W1, g_p, HMLP);

    score_csr_kernel<<<N, 256>>>(ej, noise, W2, b2);

    for (int level = 0; level < 4; level++) {
        hist_pass_kernel<<<512, 256>>>(level);
        scan_pass_kernel<<<1, 1>>>(level);
    }

    scatter_gt_eq_kernel<<<1024, 256>>>(A, ei, ej, out);
    scatter_eq_kernel<<<4, 1024>>>(A, ei, ej, out);
}